// round 6
// baseline (speedup 1.0000x reference)
#include <cuda_runtime.h>

// LightGCN 3-layer propagation on GB300 (sm_103a) — CSR gather, deferred output.
// Round 5: warp-per-row (no divergence waste between paired rows) and 4-wide
// software-pipelined gather loop (MLP=4 on the L2-latency-bound v loads).
//   layer1: hA[r] = sum norm*x[col]          (x = concat(ue,ie))
//   layer2: hB[r] = sum norm*hA[col]
//   layer3: out[r] = 0.25*(x + hA + hB + sum norm*hB[col])

#define NU 200000
#define NI 100000
#define NN 300000
#define DIM 64
#define NE 1200000
#define NBLK ((NN + 1023) / 1024)   // 293 scan blocks

struct Edge { int c; float nm; };

__device__ int   g_cnt[NN];
__device__ int   g_offs[NN];
__device__ int   g_cur[NN];
__device__ int   g_bsum[NBLK];
__device__ float g_dinv[NN];
__device__ Edge  g_edge[NE];
__device__ float g_hA[(size_t)NN * DIM];
__device__ float g_hB[(size_t)NN * DIM];

__global__ void k_zero_cnt() {
    int i = blockIdx.x * blockDim.x + threadIdx.x;
    if (i < NN) g_cnt[i] = 0;
}

__global__ void k_count(const int* __restrict__ row) {
    int e = blockIdx.x * blockDim.x + threadIdx.x;
    if (e < NE) atomicAdd(&g_cnt[row[e]], 1);
}

// Block-level exclusive scan of g_cnt; also computes dinv.
__global__ void k_scan1() {
    __shared__ int sh[1024];
    int i = blockIdx.x * 1024 + threadIdx.x;
    int v = (i < NN) ? g_cnt[i] : 0;
    if (i < NN) g_dinv[i] = (v > 0) ? rsqrtf((float)v) : 0.0f;
    sh[threadIdx.x] = v;
    __syncthreads();
    for (int off = 1; off < 1024; off <<= 1) {
        int t = (threadIdx.x >= off) ? sh[threadIdx.x - off] : 0;
        __syncthreads();
        sh[threadIdx.x] += t;
        __syncthreads();
    }
    if (i < NN) g_offs[i] = sh[threadIdx.x] - v;
    if (threadIdx.x == 1023) g_bsum[blockIdx.x] = sh[1023];
}

// Each block sums the partials below it for its base; finalize offs + cursors.
__global__ void k_scan2() {
    __shared__ int base_sh;
    int b = blockIdx.x;
    if (threadIdx.x < 32) {
        int s = 0;
        for (int j = threadIdx.x; j < b; j += 32) s += g_bsum[j];
        #pragma unroll
        for (int o = 16; o; o >>= 1) s += __shfl_down_sync(0xffffffffu, s, o);
        if (threadIdx.x == 0) base_sh = s;
    }
    __syncthreads();
    int i = b * 1024 + threadIdx.x;
    if (i < NN) {
        int o = g_offs[i] + base_sh;
        g_offs[i] = o;
        g_cur[i]  = o;
    }
}

__global__ void k_fill(const int* __restrict__ row, const int* __restrict__ col) {
    int e = blockIdx.x * blockDim.x + threadIdx.x;
    if (e < NE) {
        int r = row[e], c = col[e];
        int pos = atomicAdd(&g_cur[r], 1);
        Edge ed;
        ed.c  = c;
        ed.nm = __ldg(&g_dinv[r]) * __ldg(&g_dinv[c]);
        g_edge[pos] = ed;
    }
}

// --- Gather core: one warp per destination row, 32 lanes x float2 slices. ---
// src row stride = 32 float2. fromEmb: read concat(ue, ie) virtually.

__device__ __forceinline__ float2 fetch_f2(
    int c, int lane, const float2* __restrict__ ue, const float2* __restrict__ ie,
    const float2* __restrict__ src, int fromEmb)
{
    if (fromEmb)
        return (c < NU) ? __ldg(&ue[(size_t)c * 32 + lane])
                        : __ldg(&ie[(size_t)(c - NU) * 32 + lane]);
    return __ldg(&src[(size_t)c * 32 + lane]);
}

__device__ __forceinline__ float2 row_gather(
    int r, int lane, const float2* __restrict__ ue, const float2* __restrict__ ie,
    const float2* __restrict__ src, int fromEmb)
{
    int start = g_offs[r];
    int cnt   = g_cnt[r];
    const int2* __restrict__ ep = reinterpret_cast<const int2*>(g_edge) + start;

    float2 acc = make_float2(0.f, 0.f);
    int j = 0;
    // 4-wide: batch edge loads, then batch v gathers (MLP=4), then FMAs.
    for (; j + 3 < cnt; j += 4) {
        int2 e0 = __ldg(&ep[j + 0]);
        int2 e1 = __ldg(&ep[j + 1]);
        int2 e2 = __ldg(&ep[j + 2]);
        int2 e3 = __ldg(&ep[j + 3]);
        float2 v0 = fetch_f2(e0.x, lane, ue, ie, src, fromEmb);
        float2 v1 = fetch_f2(e1.x, lane, ue, ie, src, fromEmb);
        float2 v2 = fetch_f2(e2.x, lane, ue, ie, src, fromEmb);
        float2 v3 = fetch_f2(e3.x, lane, ue, ie, src, fromEmb);
        float n0 = __int_as_float(e0.y), n1 = __int_as_float(e1.y);
        float n2 = __int_as_float(e2.y), n3 = __int_as_float(e3.y);
        acc.x += n0 * v0.x; acc.y += n0 * v0.y;
        acc.x += n1 * v1.x; acc.y += n1 * v1.y;
        acc.x += n2 * v2.x; acc.y += n2 * v2.y;
        acc.x += n3 * v3.x; acc.y += n3 * v3.y;
    }
    if (j + 1 < cnt) {   // 2-wide step
        int2 e0 = __ldg(&ep[j + 0]);
        int2 e1 = __ldg(&ep[j + 1]);
        float2 v0 = fetch_f2(e0.x, lane, ue, ie, src, fromEmb);
        float2 v1 = fetch_f2(e1.x, lane, ue, ie, src, fromEmb);
        float n0 = __int_as_float(e0.y), n1 = __int_as_float(e1.y);
        acc.x += n0 * v0.x; acc.y += n0 * v0.y;
        acc.x += n1 * v1.x; acc.y += n1 * v1.y;
        j += 2;
    }
    if (j < cnt) {       // final single
        int2 e0 = __ldg(&ep[j]);
        float2 v0 = fetch_f2(e0.x, lane, ue, ie, src, fromEmb);
        float n0 = __int_as_float(e0.y);
        acc.x += n0 * v0.x; acc.y += n0 * v0.y;
    }
    return acc;
}

// Layer 1: hA = A_norm @ x
__global__ void __launch_bounds__(256) k_layer1(
    const float2* __restrict__ ue, const float2* __restrict__ ie)
{
    int t = blockIdx.x * blockDim.x + threadIdx.x;
    int r = t >> 5;
    if (r >= NN) return;
    int lane = t & 31;
    float2 acc = row_gather(r, lane, ue, ie, nullptr, 1);
    reinterpret_cast<float2*>(g_hA)[(size_t)r * 32 + lane] = acc;
}

// Layer 2: hB = A_norm @ hA
__global__ void __launch_bounds__(256) k_layer2() {
    int t = blockIdx.x * blockDim.x + threadIdx.x;
    int r = t >> 5;
    if (r >= NN) return;
    int lane = t & 31;
    float2 acc = row_gather(r, lane, nullptr, nullptr, (const float2*)g_hA, 0);
    reinterpret_cast<float2*>(g_hB)[(size_t)r * 32 + lane] = acc;
}

// Layer 3: out = 0.25 * (x + hA + hB + A_norm @ hB)
__global__ void __launch_bounds__(256) k_layer3(
    const float2* __restrict__ ue, const float2* __restrict__ ie,
    float2* __restrict__ out)
{
    int t = blockIdx.x * blockDim.x + threadIdx.x;
    int r = t >> 5;
    if (r >= NN) return;
    int lane = t & 31;

    float2 h3 = row_gather(r, lane, nullptr, nullptr, (const float2*)g_hB, 0);

    size_t oi = (size_t)r * 32 + lane;
    float2 x  = (r < NU) ? __ldg(&ue[oi]) : __ldg(&ie[(size_t)(r - NU) * 32 + lane]);
    float2 h1 = reinterpret_cast<const float2*>(g_hA)[oi];
    float2 h2 = reinterpret_cast<const float2*>(g_hB)[oi];

    float2 o;
    o.x = 0.25f * (x.x + h1.x + h2.x + h3.x);
    o.y = 0.25f * (x.y + h1.y + h2.y + h3.y);
    out[oi] = o;
}

extern "C" void kernel_launch(void* const* d_in, const int* in_sizes, int n_in,
                              void* d_out, int out_size) {
    const float* ue = (const float*)d_in[0];
    const float* ie = (const float*)d_in[1];
    const int*   ei = (const int*)d_in[2];
    const int* row = ei;
    const int* col = ei + NE;
    float2* out = (float2*)d_out;

    const int B = 256;
    const int gN = (NN + B - 1) / B;
    const int gE = (NE + B - 1) / B;
    const int gL = ((NN * 32) + B - 1) / B;   // one warp per row

    // CSR build
    k_zero_cnt<<<gN, B>>>();
    k_count<<<gE, B>>>(row);
    k_scan1<<<NBLK, 1024>>>();
    k_scan2<<<NBLK, 1024>>>();
    k_fill<<<gE, B>>>(row, col);

    // Layers
    k_layer1<<<gL, B>>>((const float2*)ue, (const float2*)ie);
    k_layer2<<<gL, B>>>();
    k_layer3<<<gL, B>>>((const float2*)ue, (const float2*)ie, out);
}

// round 7
// speedup vs baseline: 1.1504x; 1.1504x over previous
#include <cuda_runtime.h>

// LightGCN 3-layer propagation on GB300 (sm_103a) — CSR gather, deferred output.
// Round 6: Round-4 geometry (16 lanes/row, float4 = LDG.128 gathers) + 4-wide
// software-pipelined inner loop (MLP~4 on the L2-latency-bound v loads).
//   layer1: hA[r] = sum norm*x[col]          (x = concat(ue,ie))
//   layer2: hB[r] = sum norm*hA[col]
//   layer3: out[r] = 0.25*(x + hA + hB + sum norm*hB[col])

#define NU 200000
#define NI 100000
#define NN 300000
#define DIM 64
#define NE 1200000
#define NBLK ((NN + 1023) / 1024)   // 293 scan blocks

struct Edge { int c; float nm; };

__device__ int   g_cnt[NN];
__device__ int   g_offs[NN];
__device__ int   g_cur[NN];
__device__ int   g_bsum[NBLK];
__device__ float g_dinv[NN];
__device__ Edge  g_edge[NE];
__device__ float g_hA[(size_t)NN * DIM];
__device__ float g_hB[(size_t)NN * DIM];

__global__ void k_zero_cnt() {
    int i = blockIdx.x * blockDim.x + threadIdx.x;
    if (i < NN) g_cnt[i] = 0;
}

__global__ void k_count(const int* __restrict__ row) {
    int e = blockIdx.x * blockDim.x + threadIdx.x;
    if (e < NE) atomicAdd(&g_cnt[row[e]], 1);
}

// Block-level exclusive scan of g_cnt; also computes dinv.
__global__ void k_scan1() {
    __shared__ int sh[1024];
    int i = blockIdx.x * 1024 + threadIdx.x;
    int v = (i < NN) ? g_cnt[i] : 0;
    if (i < NN) g_dinv[i] = (v > 0) ? rsqrtf((float)v) : 0.0f;
    sh[threadIdx.x] = v;
    __syncthreads();
    for (int off = 1; off < 1024; off <<= 1) {
        int t = (threadIdx.x >= off) ? sh[threadIdx.x - off] : 0;
        __syncthreads();
        sh[threadIdx.x] += t;
        __syncthreads();
    }
    if (i < NN) g_offs[i] = sh[threadIdx.x] - v;
    if (threadIdx.x == 1023) g_bsum[blockIdx.x] = sh[1023];
}

// Each block sums the partials below it for its base; finalize offs + cursors.
__global__ void k_scan2() {
    __shared__ int base_sh;
    int b = blockIdx.x;
    if (threadIdx.x < 32) {
        int s = 0;
        for (int j = threadIdx.x; j < b; j += 32) s += g_bsum[j];
        #pragma unroll
        for (int o = 16; o; o >>= 1) s += __shfl_down_sync(0xffffffffu, s, o);
        if (threadIdx.x == 0) base_sh = s;
    }
    __syncthreads();
    int i = b * 1024 + threadIdx.x;
    if (i < NN) {
        int o = g_offs[i] + base_sh;
        g_offs[i] = o;
        g_cur[i]  = o;
    }
}

__global__ void k_fill(const int* __restrict__ row, const int* __restrict__ col) {
    int e = blockIdx.x * blockDim.x + threadIdx.x;
    if (e < NE) {
        int r = row[e], c = col[e];
        int pos = atomicAdd(&g_cur[r], 1);
        Edge ed;
        ed.c  = c;
        ed.nm = __ldg(&g_dinv[r]) * __ldg(&g_dinv[c]);
        g_edge[pos] = ed;
    }
}

// --- Gather core: 16 lanes per row, one float4 (LDG.128) slice per lane. ---

__device__ __forceinline__ float4 fetch_f4(
    int c, int li, const float4* __restrict__ ue, const float4* __restrict__ ie,
    const float4* __restrict__ src, int fromEmb)
{
    if (fromEmb)
        return (c < NU) ? __ldg(&ue[(size_t)c * 16 + li])
                        : __ldg(&ie[(size_t)(c - NU) * 16 + li]);
    return __ldg(&src[(size_t)c * 16 + li]);
}

__device__ __forceinline__ float4 row_gather(
    int r, int li, const float4* __restrict__ ue, const float4* __restrict__ ie,
    const float4* __restrict__ src, int fromEmb)
{
    int start = g_offs[r];
    int cnt   = g_cnt[r];
    const int2* __restrict__ ep = reinterpret_cast<const int2*>(g_edge) + start;

    float4 acc = make_float4(0.f, 0.f, 0.f, 0.f);
    int j = 0;
    // 4-wide: batch the edge loads, then the v gathers (MLP~4), then FMAs.
    for (; j + 3 < cnt; j += 4) {
        int2 e0 = __ldg(&ep[j + 0]);
        int2 e1 = __ldg(&ep[j + 1]);
        int2 e2 = __ldg(&ep[j + 2]);
        int2 e3 = __ldg(&ep[j + 3]);
        float4 v0 = fetch_f4(e0.x, li, ue, ie, src, fromEmb);
        float4 v1 = fetch_f4(e1.x, li, ue, ie, src, fromEmb);
        float4 v2 = fetch_f4(e2.x, li, ue, ie, src, fromEmb);
        float4 v3 = fetch_f4(e3.x, li, ue, ie, src, fromEmb);
        float n0 = __int_as_float(e0.y), n1 = __int_as_float(e1.y);
        float n2 = __int_as_float(e2.y), n3 = __int_as_float(e3.y);
        acc.x += n0 * v0.x; acc.y += n0 * v0.y; acc.z += n0 * v0.z; acc.w += n0 * v0.w;
        acc.x += n1 * v1.x; acc.y += n1 * v1.y; acc.z += n1 * v1.z; acc.w += n1 * v1.w;
        acc.x += n2 * v2.x; acc.y += n2 * v2.y; acc.z += n2 * v2.z; acc.w += n2 * v2.w;
        acc.x += n3 * v3.x; acc.y += n3 * v3.y; acc.z += n3 * v3.z; acc.w += n3 * v3.w;
    }
    if (j + 1 < cnt) {   // 2-wide step
        int2 e0 = __ldg(&ep[j + 0]);
        int2 e1 = __ldg(&ep[j + 1]);
        float4 v0 = fetch_f4(e0.x, li, ue, ie, src, fromEmb);
        float4 v1 = fetch_f4(e1.x, li, ue, ie, src, fromEmb);
        float n0 = __int_as_float(e0.y), n1 = __int_as_float(e1.y);
        acc.x += n0 * v0.x; acc.y += n0 * v0.y; acc.z += n0 * v0.z; acc.w += n0 * v0.w;
        acc.x += n1 * v1.x; acc.y += n1 * v1.y; acc.z += n1 * v1.z; acc.w += n1 * v1.w;
        j += 2;
    }
    if (j < cnt) {       // final single
        int2 e0 = __ldg(&ep[j]);
        float4 v0 = fetch_f4(e0.x, li, ue, ie, src, fromEmb);
        float n0 = __int_as_float(e0.y);
        acc.x += n0 * v0.x; acc.y += n0 * v0.y; acc.z += n0 * v0.z; acc.w += n0 * v0.w;
    }
    return acc;
}

// Layer 1: hA = A_norm @ x
__global__ void __launch_bounds__(256) k_layer1(
    const float4* __restrict__ ue, const float4* __restrict__ ie)
{
    int t = blockIdx.x * blockDim.x + threadIdx.x;
    int r = t >> 4;
    if (r >= NN) return;
    int li = t & 15;
    float4 acc = row_gather(r, li, ue, ie, nullptr, 1);
    reinterpret_cast<float4*>(g_hA)[(size_t)r * 16 + li] = acc;
}

// Layer 2: hB = A_norm @ hA
__global__ void __launch_bounds__(256) k_layer2() {
    int t = blockIdx.x * blockDim.x + threadIdx.x;
    int r = t >> 4;
    if (r >= NN) return;
    int li = t & 15;
    float4 acc = row_gather(r, li, nullptr, nullptr, (const float4*)g_hA, 0);
    reinterpret_cast<float4*>(g_hB)[(size_t)r * 16 + li] = acc;
}

// Layer 3: out = 0.25 * (x + hA + hB + A_norm @ hB)
__global__ void __launch_bounds__(256) k_layer3(
    const float4* __restrict__ ue, const float4* __restrict__ ie,
    float4* __restrict__ out)
{
    int t = blockIdx.x * blockDim.x + threadIdx.x;
    int r = t >> 4;
    if (r >= NN) return;
    int li = t & 15;

    float4 h3 = row_gather(r, li, nullptr, nullptr, (const float4*)g_hB, 0);

    size_t oi = (size_t)r * 16 + li;
    float4 x  = (r < NU) ? __ldg(&ue[oi]) : __ldg(&ie[(size_t)(r - NU) * 16 + li]);
    float4 h1 = reinterpret_cast<const float4*>(g_hA)[oi];
    float4 h2 = reinterpret_cast<const float4*>(g_hB)[oi];

    float4 o;
    o.x = 0.25f * (x.x + h1.x + h2.x + h3.x);
    o.y = 0.25f * (x.y + h1.y + h2.y + h3.y);
    o.z = 0.25f * (x.z + h1.z + h2.z + h3.z);
    o.w = 0.25f * (x.w + h1.w + h2.w + h3.w);
    out[oi] = o;
}

extern "C" void kernel_launch(void* const* d_in, const int* in_sizes, int n_in,
                              void* d_out, int out_size) {
    const float* ue = (const float*)d_in[0];
    const float* ie = (const float*)d_in[1];
    const int*   ei = (const int*)d_in[2];
    const int* row = ei;
    const int* col = ei + NE;
    float4* out = (float4*)d_out;

    const int B = 256;
    const int gN = (NN + B - 1) / B;
    const int gE = (NE + B - 1) / B;
    const int gL = ((NN * 16) + B - 1) / B;   // 16 lanes per row

    // CSR build
    k_zero_cnt<<<gN, B>>>();
    k_count<<<gE, B>>>(row);
    k_scan1<<<NBLK, 1024>>>();
    k_scan2<<<NBLK, 1024>>>();
    k_fill<<<gE, B>>>(row, col);

    // Layers
    k_layer1<<<gL, B>>>((const float4*)ue, (const float4*)ie);
    k_layer2<<<gL, B>>>();
    k_layer3<<<gL, B>>>((const float4*)ue, (const float4*)ie, out);
}